// round 6
// baseline (speedup 1.0000x reference)
#include <cuda_runtime.h>
#include <math.h>

#define BB   2
#define TT   1024
#define HH   1024
#define NHD  16
#define NKVH 4
#define HDD  64
#define NE   64
#define TOPK 8
#define NI   512
#define NTOK (BB*TT)   // 2048
#define MTILE 32

typedef unsigned long long ull;

__device__ __forceinline__ ull pk2(float a, float b) {
    ull r; asm("mov.b64 %0,{%1,%2};" : "=l"(r) : "f"(a), "f"(b)); return r;
}
__device__ __forceinline__ void fma2(ull& d, ull a, ull b) {
    asm("fma.rn.f32x2 %0,%1,%2,%0;" : "+l"(d) : "l"(a), "l"(b));
}
__device__ __forceinline__ void mul2(ull& d, ull a) {
    asm("mul.rn.f32x2 %0,%0,%1;" : "+l"(d) : "l"(a));
}
__device__ __forceinline__ float2 up2(ull v) {
    float2 f; asm("mov.b64 {%0,%1},%2;" : "=f"(f.x), "=f"(f.y) : "l"(v)); return f;
}

// ---------------- scratch (device globals) ----------
__device__ float g_h  [NTOK*HH];
__device__ float g_q  [NTOK*NHD*HDD];
__device__ float g_k  [NTOK*NKVH*HDD];
__device__ float g_v  [NTOK*NKVH*HDD];
__device__ float g_att[NTOK*NHD*HDD];
__device__ float g_f  [NTOK*HH];
__device__ float g_y  [(size_t)NTOK*TOPK*HH];   // per-(token,k) expert outputs
__device__ int   g_cnt[NE];
__device__ int   g_tok[NE*NTOK];
__device__ float g_scr[NE*NTOK];
__device__ int   g_slt[NE*NTOK];

// ---------------- rmsnorm ----------------
__global__ void rmsnorm_k(const float* __restrict__ x, const float* __restrict__ w,
                          float* __restrict__ o) {
    int row = blockIdx.x;
    const float* xr = x + (size_t)row * HH;
    float ss = 0.f;
    for (int i = threadIdx.x; i < HH; i += 256) { float v = xr[i]; ss += v * v; }
    __shared__ float red[256];
    red[threadIdx.x] = ss; __syncthreads();
    for (int s = 128; s > 0; s >>= 1) {
        if (threadIdx.x < s) red[threadIdx.x] += red[threadIdx.x + s];
        __syncthreads();
    }
    float inv = rsqrtf(red[0] * (1.0f / HH) + 1e-6f);
    float* op = o + (size_t)row * HH;
    for (int i = threadIdx.x; i < HH; i += 256) op[i] = xr[i] * inv * w[i];
}

// ---------------- generic tiled SGEMM (f32x2): C = A@B (+R) ----------------
__global__ __launch_bounds__(256)
void sgemm_k(const float* __restrict__ A, const float* __restrict__ B,
             const float* __restrict__ R, float* __restrict__ C,
             int M, int N, int K) {
    __shared__ ull   As2[16][64];   // duplicated splats
    __shared__ float Bs[16][64];
    int tid = threadIdx.x;
    int tx = tid & 15, ty = tid >> 4;
    const float* Ab = A + (size_t)blockIdx.y * 64 * K;
    const float* Bb = B + (size_t)blockIdx.x * 64;
    ull acc[4][2];
    #pragma unroll
    for (int i = 0; i < 4; i++) { acc[i][0] = 0ull; acc[i][1] = 0ull; }

    for (int k0 = 0; k0 < K; k0 += 16) {
        #pragma unroll
        for (int l = 0; l < 4; l++) {
            int idx = tid + l * 256;
            int m = idx >> 4, k = idx & 15;
            float v = Ab[(size_t)m * K + k0 + k];
            As2[k][m] = pk2(v, v);
        }
        #pragma unroll
        for (int l = 0; l < 4; l++) {
            int idx = tid + l * 256;
            int k = idx >> 6, n = idx & 63;
            Bs[k][n] = Bb[(size_t)(k0 + k) * N + n];
        }
        __syncthreads();
        #pragma unroll
        for (int k = 0; k < 16; k++) {
            const ull* brow = (const ull*)Bs[k];
            ull b0 = brow[tx * 2], b1 = brow[tx * 2 + 1];
            #pragma unroll
            for (int i = 0; i < 4; i++) {
                ull a2 = As2[k][ty * 4 + i];
                fma2(acc[i][0], a2, b0);
                fma2(acc[i][1], a2, b1);
            }
        }
        __syncthreads();
    }
    #pragma unroll
    for (int i = 0; i < 4; i++) {
        int m = blockIdx.y * 64 + ty * 4 + i;
        int nb = blockIdx.x * 64 + tx * 4;
        float2 c0 = up2(acc[i][0]), c1 = up2(acc[i][1]);
        float4 v = make_float4(c0.x, c0.y, c1.x, c1.y);
        if (R) {
            float4 r = *(const float4*)(R + (size_t)m * N + nb);
            v.x += r.x; v.y += r.y; v.z += r.z; v.w += r.w;
        }
        *(float4*)(C + (size_t)m * N + nb) = v;
    }
}

// ---------------- fused QKV GEMM + RoPE epilogue ----------------
// grid (24, NTOK/64): bx 0-15 -> Q head bx; 16-19 -> K head; 20-23 -> V head
__global__ __launch_bounds__(256)
void qkv_k(const float* __restrict__ A,
           const float* __restrict__ Wq, const float* __restrict__ Wk,
           const float* __restrict__ Wv,
           const float* __restrict__ cosp, const float* __restrict__ sinp,
           float* __restrict__ qo, float* __restrict__ ko, float* __restrict__ vo) {
    __shared__ ull   As2[16][64];
    __shared__ float Bs[16][64];
    __shared__ float Cs[64][65];
    int bx = blockIdx.x;
    const float* Bp; float* O; int N, colb; bool rope;
    if (bx < 16)      { Bp = Wq; O = qo; N = 1024; colb = bx * 64;        rope = true;  }
    else if (bx < 20) { Bp = Wk; O = ko; N = 256;  colb = (bx - 16) * 64; rope = true;  }
    else              { Bp = Wv; O = vo; N = 256;  colb = (bx - 20) * 64; rope = false; }

    int tid = threadIdx.x;
    int tx = tid & 15, ty = tid >> 4;
    const float* Ab = A + (size_t)blockIdx.y * 64 * HH;
    const float* Bb = Bp + colb;
    ull acc[4][2];
    #pragma unroll
    for (int i = 0; i < 4; i++) { acc[i][0] = 0ull; acc[i][1] = 0ull; }

    for (int k0 = 0; k0 < HH; k0 += 16) {
        #pragma unroll
        for (int l = 0; l < 4; l++) {
            int idx = tid + l * 256;
            int m = idx >> 4, k = idx & 15;
            float v = Ab[(size_t)m * HH + k0 + k];
            As2[k][m] = pk2(v, v);
        }
        #pragma unroll
        for (int l = 0; l < 4; l++) {
            int idx = tid + l * 256;
            int k = idx >> 6, n = idx & 63;
            Bs[k][n] = Bb[(size_t)(k0 + k) * N + n];
        }
        __syncthreads();
        #pragma unroll
        for (int k = 0; k < 16; k++) {
            const ull* brow = (const ull*)Bs[k];
            ull b0 = brow[tx * 2], b1 = brow[tx * 2 + 1];
            #pragma unroll
            for (int i = 0; i < 4; i++) {
                ull a2 = As2[k][ty * 4 + i];
                fma2(acc[i][0], a2, b0);
                fma2(acc[i][1], a2, b1);
            }
        }
        __syncthreads();
    }
    #pragma unroll
    for (int i = 0; i < 4; i++) {
        float2 c0 = up2(acc[i][0]), c1 = up2(acc[i][1]);
        int r = ty * 4 + i, c = tx * 4;
        Cs[r][c] = c0.x; Cs[r][c + 1] = c0.y; Cs[r][c + 2] = c1.x; Cs[r][c + 3] = c1.y;
    }
    __syncthreads();
    // epilogue: RoPE + write (one head tile == 64 cols == one head)
    #pragma unroll
    for (int l = 0; l < 16; l++) {
        int e = tid + l * 256;        // 0..4095
        int r = e >> 6, d = e & 63;
        int m = blockIdx.y * 64 + r;
        int t = m & (TT - 1);
        float u = Cs[r][d];
        float val;
        if (rope) {
            float cv = cosp[t * HDD + d], sv = sinp[t * HDD + d];
            float w = Cs[r][d ^ 32];
            val = (d < 32) ? (u * cv - w * sv) : (u * cv + w * sv);
        } else val = u;
        O[(size_t)m * N + colb + d] = val;
    }
}

// ---------------- causal GQA attention (f32x2 online softmax) ----------------
__global__ __launch_bounds__(128)
void attn_k(const float* __restrict__ q, const float* __restrict__ k,
            const float* __restrict__ v, float* __restrict__ o) {
    __shared__ float Ks[64][HDD];
    __shared__ float Vs[64][HDD];
    int bh  = blockIdx.y;
    int b   = bh >> 4;
    int h   = bh & 15;
    int kvh = h >> 2;
    int bx  = gridDim.x - 1 - blockIdx.x;   // heavy blocks first
    int qi  = bx * 128 + threadIdx.x;

    ull q2[32], o2[32];
    const ull* qp = (const ull*)(q + (((size_t)(b * TT + qi)) * NHD + h) * HDD);
    ull sc = pk2(0.125f, 0.125f);
    #pragma unroll
    for (int d = 0; d < 32; d++) { q2[d] = qp[d]; mul2(q2[d], sc); o2[d] = 0ull; }
    float m = -1e30f, l = 0.f;

    int qmax = bx * 128 + 127;
    for (int j0 = 0; j0 <= qmax; j0 += 64) {
        __syncthreads();
        for (int e = threadIdx.x; e < 64 * (HDD / 4); e += 128) {
            int jj = e >> 4;
            int dd = (e & 15) * 4;
            size_t base = (((size_t)(b * TT + j0 + jj)) * NKVH + kvh) * HDD + dd;
            *(float4*)&Ks[jj][dd] = *(const float4*)(k + base);
            *(float4*)&Vs[jj][dd] = *(const float4*)(v + base);
        }
        __syncthreads();
        int jend = qi - j0 + 1;
        if (jend > 64) jend = 64;
        for (int jj = 0; jj < jend; jj++) {
            const ull* kr = (const ull*)Ks[jj];
            ull sA = 0ull, sB = 0ull, sC = 0ull, sD = 0ull;
            #pragma unroll
            for (int d = 0; d < 32; d += 4) {
                fma2(sA, q2[d],     kr[d]);
                fma2(sB, q2[d + 1], kr[d + 1]);
                fma2(sC, q2[d + 2], kr[d + 2]);
                fma2(sD, q2[d + 3], kr[d + 3]);
            }
            float2 fA = up2(sA), fB = up2(sB), fC = up2(sC), fD = up2(sD);
            float s = (fA.x + fA.y) + (fB.x + fB.y) + (fC.x + fC.y) + (fD.x + fD.y);
            if (s > m) {
                float fexp = __expf(m - s);
                ull f2 = pk2(fexp, fexp);
                l *= fexp;
                #pragma unroll
                for (int d = 0; d < 32; d++) mul2(o2[d], f2);
                m = s;
            }
            float p = __expf(s - m);
            l += p;
            ull p2 = pk2(p, p);
            const ull* vr = (const ull*)Vs[jj];
            #pragma unroll
            for (int d = 0; d < 32; d++) fma2(o2[d], p2, vr[d]);
        }
    }
    float invl = 1.f / l;
    ull il2 = pk2(invl, invl);
    ull* op = (ull*)(o + (((size_t)(b * TT + qi)) * NHD + h) * HDD);
    #pragma unroll
    for (int d = 0; d < 32; d++) { mul2(o2[d], il2); op[d] = o2[d]; }
}

// ---------------- router top-8 select + expert scatter ----------------
__global__ void zero_cnt_k() {
    if (threadIdx.x < NE) g_cnt[threadIdx.x] = 0;
}

__global__ void topk_k(const float* __restrict__ logits) {
    int n = blockIdx.x * blockDim.x + threadIdx.x;
    if (n >= NTOK) return;
    float lg[NE];
    for (int e = 0; e < NE; e++) lg[e] = logits[(size_t)n * NE + e];
    int   ids[TOPK];
    float vals[TOPK];
    for (int kk = 0; kk < TOPK; kk++) {
        int best = 0; float bv = lg[0];
        for (int e = 1; e < NE; e++) if (lg[e] > bv) { bv = lg[e]; best = e; }
        ids[kk] = best; vals[kk] = bv; lg[best] = -1e30f;
    }
    float mx = vals[0], sum = 0.f;
    for (int kk = 0; kk < TOPK; kk++) { vals[kk] = __expf(vals[kk] - mx); sum += vals[kk]; }
    float inv = 1.f / sum;
    for (int kk = 0; kk < TOPK; kk++) {
        int e = ids[kk];
        int p = atomicAdd(&g_cnt[e], 1);
        g_tok[e * NTOK + p] = n;
        g_scr[e * NTOK + p] = vals[kk] * inv;
        g_slt[e * NTOK + p] = n * TOPK + kk;
    }
}

// ---------------- grouped MoE (f32x2): per (expert, 32-token tile) ----------------
__global__ __launch_bounds__(256)
void moe_k(const float* __restrict__ f, const float* __restrict__ Wg,
           const float* __restrict__ Wu, const float* __restrict__ Wd,
           float* __restrict__ y) {
    int e    = blockIdx.x;
    int tile = blockIdx.y;
    int nt   = g_cnt[e];
    int t0   = tile * MTILE;
    if (t0 >= nt) return;

    extern __shared__ char smraw[];
    ull   (*Fs2)[64] = (ull(*)[64])smraw;                     // 16 KB, splat-duplicated
    float (*Gs)[NI]  = (float(*)[NI])(smraw + 16384);         // 64 KB
    int*   toks = (int*)(smraw + 16384 + 65536);
    float* scs  = (float*)(toks + MTILE);
    int*   slts = (int*)(scs + MTILE);

    int tid = threadIdx.x;
    if (tid < MTILE) {
        int ti = t0 + tid;
        toks[tid] = (ti < nt) ? g_tok[e * NTOK + ti] : -1;
        scs[tid]  = (ti < nt) ? g_scr[e * NTOK + ti] : 0.f;
        slts[tid] = (ti < nt) ? g_slt[e * NTOK + ti] : -1;
    }
    __syncthreads();

    // ---- gate/up: thread owns intermediate cols (2*tid, 2*tid+1) ----
    ull ag[MTILE], au[MTILE];
    #pragma unroll
    for (int t = 0; t < MTILE; t++) { ag[t] = 0ull; au[t] = 0ull; }

    const float* Wge = Wg + (size_t)e * HH * NI + 2 * tid;
    const float* Wue = Wu + (size_t)e * HH * NI + 2 * tid;

    for (int h0 = 0; h0 < HH; h0 += 64) {
        __syncthreads();
        #pragma unroll
        for (int l = 0; l < 2; l++) {
            int e2 = tid + l * 256;             // 0..511
            int row = e2 >> 4, c4 = (e2 & 15) * 4;
            int tk = toks[row];
            float4 val = (tk >= 0) ? *(const float4*)(f + (size_t)tk * HH + h0 + c4)
                                   : make_float4(0.f, 0.f, 0.f, 0.f);
            Fs2[row][c4]     = pk2(val.x, val.x);
            Fs2[row][c4 + 1] = pk2(val.y, val.y);
            Fs2[row][c4 + 2] = pk2(val.z, val.z);
            Fs2[row][c4 + 3] = pk2(val.w, val.w);
        }
        __syncthreads();
        #pragma unroll 2
        for (int hh = 0; hh < 64; hh++) {
            ull wg = *(const ull*)(Wge + (size_t)(h0 + hh) * NI);
            ull wu = *(const ull*)(Wue + (size_t)(h0 + hh) * NI);
            #pragma unroll
            for (int t = 0; t < MTILE; t++) {
                ull fv = Fs2[t][hh];
                fma2(ag[t], fv, wg);
                fma2(au[t], fv, wu);
            }
        }
    }
    __syncthreads();
    #pragma unroll
    for (int t = 0; t < MTILE; t++) {
        float2 g = up2(ag[t]);
        float2 u = up2(au[t]);
        float sx = g.x / (1.f + __expf(-g.x)) * u.x;
        float sy = g.y / (1.f + __expf(-g.y)) * u.y;
        *(float2*)&Gs[t][2 * tid] = make_float2(sx, sy);
    }
    __syncthreads();

    // ---- down: thread owns 4 output cols (4*tid .. 4*tid+3) ----
    ull acc[MTILE][2];
    #pragma unroll
    for (int t = 0; t < MTILE; t++) { acc[t][0] = 0ull; acc[t][1] = 0ull; }
    const float* Wde = Wd + (size_t)e * NI * HH + 4 * tid;
    #pragma unroll 2
    for (int i = 0; i < NI; i++) {
        ulonglong2 wd = *(const ulonglong2*)(Wde + (size_t)i * HH);
        #pragma unroll
        for (int t = 0; t < MTILE; t++) {
            float gv = Gs[t][i];
            ull g2 = pk2(gv, gv);
            fma2(acc[t][0], g2, wd.x);
            fma2(acc[t][1], g2, wd.y);
        }
    }
    #pragma unroll
    for (int t = 0; t < MTILE; t++) {
        int slot = slts[t];
        if (slot < 0) continue;
        float s = scs[t];
        float2 a0 = up2(acc[t][0]), a1 = up2(acc[t][1]);
        float4 v = make_float4(s * a0.x, s * a0.y, s * a1.x, s * a1.y);
        *(float4*)(y + (size_t)slot * HH + 4 * tid) = v;
    }
}

// ---------------- gather: out += sum_k y[(n,k)] ----------------
__global__ void gather_k(const float* __restrict__ y, float* __restrict__ out) {
    int n = blockIdx.x;
    int c = threadIdx.x * 4;
    const float* base = y + (size_t)n * TOPK * HH + c;
    float4 a = *(float4*)(out + (size_t)n * HH + c);
    #pragma unroll
    for (int kk = 0; kk < TOPK; kk++) {
        float4 yv = *(const float4*)(base + (size_t)kk * HH);
        a.x += yv.x; a.y += yv.y; a.z += yv.z; a.w += yv.w;
    }
    *(float4*)(out + (size_t)n * HH + c) = a;
}

// ---------------- launch ----------------
extern "C" void kernel_launch(void* const* d_in, const int* in_sizes, int n_in,
                              void* d_out, int out_size) {
    const float* x    = (const float*)d_in[0];
    const float* cosp = (const float*)d_in[1];
    const float* sinp = (const float*)d_in[2];
    const float* ln1w = (const float*)d_in[3];
    const float* ln2w = (const float*)d_in[4];
    const float* Wq   = (const float*)d_in[5];
    const float* Wk   = (const float*)d_in[6];
    const float* Wv   = (const float*)d_in[7];
    const float* Wo   = (const float*)d_in[8];
    const float* Wr   = (const float*)d_in[9];
    const float* Wg   = (const float*)d_in[10];
    const float* Wu   = (const float*)d_in[11];
    const float* Wd   = (const float*)d_in[12];

    float* out    = (float*)d_out;                       // [NTOK, HH]
    float* logits = (float*)d_out + (size_t)NTOK * HH;   // [NTOK, NE]

    float *hb, *qb, *kb, *vb, *ab, *fb, *yb;
    cudaGetSymbolAddress((void**)&hb, g_h);
    cudaGetSymbolAddress((void**)&qb, g_q);
    cudaGetSymbolAddress((void**)&kb, g_k);
    cudaGetSymbolAddress((void**)&vb, g_v);
    cudaGetSymbolAddress((void**)&ab, g_att);
    cudaGetSymbolAddress((void**)&fb, g_f);
    cudaGetSymbolAddress((void**)&yb, g_y);

    int moe_smem = 16384 + 65536 + MTILE * 12 + 64;
    cudaFuncSetAttribute(moe_k, cudaFuncAttributeMaxDynamicSharedMemorySize, moe_smem);

    // 1. rmsnorm1
    rmsnorm_k<<<NTOK, 256>>>(x, ln1w, hb);
    // 2. fused QKV + RoPE
    qkv_k<<<dim3(24, NTOK / 64), 256>>>(hb, Wq, Wk, Wv, cosp, sinp, qb, kb, vb);
    // 3. attention
    attn_k<<<dim3(TT / 128, BB * NHD), 128>>>(qb, kb, vb, ab);
    // 4. Wo + residual -> out
    sgemm_k<<<dim3(HH / 64, NTOK / 64), 256>>>(ab, Wo, x, out, NTOK, HH, HH);
    // 5. rmsnorm2
    rmsnorm_k<<<NTOK, 256>>>(out, ln2w, fb);
    // 6. router logits -> second output region
    sgemm_k<<<dim3(NE / 64, NTOK / 64), 256>>>(fb, Wr, nullptr, logits, NTOK, NE, HH);
    // 7-8. top-8 + scatter
    zero_cnt_k<<<1, 64>>>();
    topk_k<<<(NTOK + 255) / 256, 256>>>(logits);
    // 9. MoE -> per-slot scratch
    moe_k<<<dim3(NE, NTOK / MTILE), 256, moe_smem>>>(fb, Wg, Wu, Wd, yb);
    // 10. gather slots into out
    gather_k<<<NTOK, 256>>>(yb, out);
}